// round 12
// baseline (speedup 1.0000x reference)
#include <cuda_runtime.h>
#include <cuda_fp16.h>
#include <math.h>
#include <stdint.h>

#define T_TOK 2048
#define HID   1024
#define NEXP  64
#define TOPK  8
#define ISZ   512
#define GRP   128

// ================= helpers ========================================================
__device__ __forceinline__ uint32_t smem_to_u32(const void* p) {
    uint32_t a;
    asm("{ .reg .u64 t; cvta.to.shared.u64 t, %1; cvt.u32.u64 %0, t; }" : "=r"(a) : "l"(p));
    return a;
}
#define SW128(o) ((o) ^ (((o) >> 3) & 0x70))

#define CP16(dst, src) \
    asm volatile("cp.async.cg.shared.global [%0], [%1], 16;" \
                 :: "r"((uint32_t)(dst)), "l"((const void*)(src)) : "memory")
#define CP_COMMIT() asm volatile("cp.async.commit_group;" ::: "memory")
#define CP_WAIT0()  asm volatile("cp.async.wait_group 0;" ::: "memory")

__device__ __forceinline__ void ldsm4(uint32_t addr, uint32_t& r0, uint32_t& r1,
                                      uint32_t& r2, uint32_t& r3) {
    asm volatile("ldmatrix.sync.aligned.m8n8.x4.shared.b16 {%0,%1,%2,%3}, [%4];"
                 : "=r"(r0), "=r"(r1), "=r"(r2), "=r"(r3) : "r"(addr));
}
__device__ __forceinline__ void mma16816(float* c, const uint32_t* a,
                                         uint32_t b0, uint32_t b1) {
    asm volatile("mma.sync.aligned.m16n8k16.row.col.f32.f16.f16.f32 "
                 "{%0,%1,%2,%3}, {%4,%5,%6,%7}, {%8,%9}, {%0,%1,%2,%3};"
                 : "+f"(c[0]), "+f"(c[1]), "+f"(c[2]), "+f"(c[3])
                 : "r"(a[0]), "r"(a[1]), "r"(a[2]), "r"(a[3]), "r"(b0), "r"(b1));
}
// ldsm address: tile rows of 64 fp16 (128 B), SW128-swizzled, base 1024-aligned.
__device__ __forceinline__ uint32_t ldsm_addr(uint32_t tile_base, int R, int kk, int lane) {
    int g = lane >> 3;
    int row = R + ((g & 1) << 3) + (lane & 7);
    uint32_t off = (uint32_t)(row * 128 + kk * 32 + ((g >> 1) << 4));
    return tile_base + SW128(off);
}
__device__ __forceinline__ uint32_t packh2(__half a, __half b) {
    return (uint32_t)__half_as_ushort(a) | ((uint32_t)__half_as_ushort(b) << 16);
}

// ================= device scratch =================================================
__device__ __half g_W1q[33554432];   // [E*I=32768][K=1024] pre-scaled fp16, k-major
__device__ __half g_W2q[33554432];   // [E*H=65536][K=512]
__device__ __half g_Xq[2097152];     // [T=2048][1024]
__device__ __half g_Hq[8388608];     // [16384 slots][512]
__device__ float  g_O2[16777216];    // [16384 slots][1024]
__device__ int   g_topk_idx[T_TOK*TOPK];
__device__ float g_topk_w[T_TOK*TOPK];
__device__ int   g_cnt[NEXP];
__device__ int   g_base[NEXP];
__device__ int   g_pos[NEXP];
__device__ int   g_tok[T_TOK*TOPK];
__device__ float g_tw[T_TOK*TOPK];
__device__ int   g_slot[T_TOK*TOPK];
__device__ int   g_tile_e[256];
__device__ int   g_tile_off[256];
__device__ int   g_ntiles;
__device__ int   g_ticket;
__device__ int   g_ready[256];

// ================= dequant: (q-z)*s -> fp16, transposed k-major ==================
// AWQ nibble j shift = (j>>1)*4 + (j&1)*16; dense column n = c*8+j -> output row n.
#define DQ_S 260
__global__ __launch_bounds__(256) void dequant1_t(
    const int* __restrict__ qw, const int* __restrict__ qz, const float* __restrict__ sc) {
    // fold the old zero_kernel in here (runs before router in stream order)
    if (blockIdx.x == 0 && blockIdx.y == 0 && threadIdx.x < NEXP) {
        g_cnt[threadIdx.x] = 0; g_pos[threadIdx.x] = 0;
    }
    int c0 = blockIdx.x * 8;       // word columns (of 4096)
    int k0 = blockIdx.y * 256;     // k tile (of 1024)
    extern __shared__ char smraw[];
    __half* sh = (__half*)smraw;   // [64 n][260 k]
    int tid = threadIdx.x;
    int c = tid & 7, kb = tid >> 3;
#pragma unroll
    for (int r = 0; r < 8; r++) {
        int k = k0 + kb + r * 32;
        unsigned q = (unsigned)qw[(size_t)k * 4096 + c0 + c];
        unsigned z = (unsigned)qz[(size_t)(k >> 7) * 4096 + c0 + c];
        const float* srow = sc + (size_t)(k >> 7) * 32768 + (size_t)(c0 + c) * 8;
#pragma unroll
        for (int j = 0; j < 8; j++) {
            int sh_b = ((j >> 1) << 2) + ((j & 1) << 4);
            float v = (float)((int)((q >> sh_b) & 15u) - (int)((z >> sh_b) & 15u)) * srow[j];
            sh[(c * 8 + j) * DQ_S + (k - k0)] = __float2half_rn(v);
        }
    }
    __syncthreads();
    int n = tid >> 2, qd = tid & 3;
    size_t dst = (size_t)(c0 * 8 + n) * 1024 + k0 + qd * 64;
    const uint2* s2 = (const uint2*)(sh + n * DQ_S + qd * 64);
    uint2* dp = (uint2*)(g_W1q + dst);
#pragma unroll
    for (int u = 0; u < 16; u++) dp[u] = s2[u];
}

__global__ __launch_bounds__(256) void dequant2_t(
    const int* __restrict__ qw, const int* __restrict__ qz, const float* __restrict__ sc) {
    int c0 = blockIdx.x * 8;       // word columns (of 8192)
    int k0 = blockIdx.y * 256;     // k tile (of 512)
    extern __shared__ char smraw[];
    __half* sh = (__half*)smraw;
    int tid = threadIdx.x;
    int c = tid & 7, kb = tid >> 3;
#pragma unroll
    for (int r = 0; r < 8; r++) {
        int k = k0 + kb + r * 32;
        unsigned q = (unsigned)qw[(size_t)k * 8192 + c0 + c];
        unsigned z = (unsigned)qz[(size_t)(k >> 7) * 8192 + c0 + c];
        const float* srow = sc + (size_t)(k >> 7) * 65536 + (size_t)(c0 + c) * 8;
#pragma unroll
        for (int j = 0; j < 8; j++) {
            int sh_b = ((j >> 1) << 2) + ((j & 1) << 4);
            float v = (float)((int)((q >> sh_b) & 15u) - (int)((z >> sh_b) & 15u)) * srow[j];
            sh[(c * 8 + j) * DQ_S + (k - k0)] = __float2half_rn(v);
        }
    }
    __syncthreads();
    int n = tid >> 2, qd = tid & 3;
    size_t dst = (size_t)(c0 * 8 + n) * 512 + k0 + qd * 64;
    const uint2* s2 = (const uint2*)(sh + n * DQ_S + qd * 64);
    uint2* dp = (uint2*)(g_W2q + dst);
#pragma unroll
    for (int u = 0; u < 16; u++) dp[u] = s2[u];
}

// ================= router (fused x -> fp16 conversion) ===========================
__global__ __launch_bounds__(256) void router_kernel(
    const float* __restrict__ x, const float* __restrict__ gw) {
    int tbase = blockIdx.x * 4;
    __shared__ float4 xs4[4][256];
    __shared__ float part[4][64][4];
    __shared__ float logits[4][64];
    int tid = threadIdx.x;
    for (int i = tid; i < 1024; i += 256) {
        int tt = i >> 8, cc = i & 255;
        float4 v = ((const float4*)(x + (size_t)(tbase + tt) * HID))[cc];
        xs4[tt][cc] = v;
        // fused xcvt: write fp16 copy of x
        *(uint2*)(g_Xq + (size_t)(tbase + tt) * HID + cc * 4) = make_uint2(
            packh2(__float2half_rn(v.x), __float2half_rn(v.y)),
            packh2(__float2half_rn(v.z), __float2half_rn(v.w)));
    }
    __syncthreads();
    int e = tid >> 2, p = tid & 3;
    const float4* wr = (const float4*)(gw + (size_t)e * HID);
    float s0 = 0, s1 = 0, s2 = 0, s3 = 0;
    for (int k = 0; k < 64; k++) {
        int idx = k * 4 + p;
        float4 w = wr[idx];
        float4 a0 = xs4[0][idx]; s0 += a0.x * w.x + a0.y * w.y + a0.z * w.z + a0.w * w.w;
        float4 a1 = xs4[1][idx]; s1 += a1.x * w.x + a1.y * w.y + a1.z * w.z + a1.w * w.w;
        float4 a2 = xs4[2][idx]; s2 += a2.x * w.x + a2.y * w.y + a2.z * w.z + a2.w * w.w;
        float4 a3 = xs4[3][idx]; s3 += a3.x * w.x + a3.y * w.y + a3.z * w.z + a3.w * w.w;
    }
    part[0][e][p] = s0; part[1][e][p] = s1; part[2][e][p] = s2; part[3][e][p] = s3;
    __syncthreads();
    {
        int tt = tid >> 6, ee = tid & 63;
        logits[tt][ee] = part[tt][ee][0] + part[tt][ee][1] + part[tt][ee][2] + part[tt][ee][3];
    }
    __syncthreads();
    if (tid < 4) {
        int t = tbase + tid;
        unsigned long long used = 0ull;
        int idx[8]; float lv[8];
        for (int r = 0; r < 8; r++) {
            float best = -1e30f; int bi = 0;
            for (int i = 0; i < 64; i++) {
                if (!((used >> i) & 1ull) && logits[tid][i] > best) { best = logits[tid][i]; bi = i; }
            }
            used |= 1ull << bi; idx[r] = bi; lv[r] = best;
        }
        float m = lv[0], sum = 0.f, wk[8];
        for (int r = 0; r < 8; r++) { wk[r] = expf(lv[r] - m); sum += wk[r]; }
        float inv = 1.f / sum;
        for (int r = 0; r < 8; r++) {
            g_topk_idx[t * TOPK + r] = idx[r];
            g_topk_w[t * TOPK + r]   = wk[r] * inv;
            atomicAdd(&g_cnt[idx[r]], 1);
        }
    }
}

// ================= scan (+ worklist + scheduler reset) + scatter =================
__global__ void scan_kernel() {
    int acc = 0;
    for (int i = 0; i < NEXP; i++) { g_base[i] = acc; acc += g_cnt[i]; }
    int tt = 0;
    for (int e = 0; e < NEXP; e++)
        for (int t = 0; t < g_cnt[e]; t += 128) { g_tile_e[tt] = e; g_tile_off[tt] = t; tt++; }
    g_ntiles = tt;
    g_ticket = 0;
    for (int i = 0; i < 256; i++) g_ready[i] = 0;
}

__global__ __launch_bounds__(256) void scatter_kernel() {
    int p = blockIdx.x * 256 + threadIdx.x;
    if (p >= T_TOK * TOPK) return;
    int e = g_topk_idx[p];
    int pos = g_base[e] + atomicAdd(&g_pos[e], 1);
    g_tok[pos] = p >> 3;
    g_tw[pos]  = g_topk_w[p];
    g_slot[p]  = pos;
}

// ================= fused persistent FFN (ffn1 + ffn2, ticket scheduler) ==========
// block tile 128(M) x 128(N), KC=64; 8 warps as 2(M)x4(N) -> warp tile 64x32.
// smem: tok[128]@0, tw[128]@512, double buffers @1024: {A 16KB, B 16KB} x 2.
// Tickets [0, 4*ntiles) = ffn1 items; [4*ntiles, 12*ntiles) = ffn2 items.
// ffn2 item (tile,*) spins until g_ready[tile]==4 (all 4 ffn1 ntiles of tile done).
// Grid = occupancy*SMs (host-queried) -> all CTAs co-resident -> no deadlock.
#define F_SMEM (1024 + 2 * 32768)

__global__ __launch_bounds__(256, 2) void ffn_fused() {
    extern __shared__ char smraw[];
    __shared__ int s_tk;
    int* tok_s = (int*)smraw;
    float* tw_s = (float*)(smraw + 512);
    uint32_t sb = smem_to_u32(smraw);
    int tid = threadIdx.x, lane = tid & 31, wid = tid >> 5;
    int wm = wid & 1, wn = wid >> 1;
    int n1 = g_ntiles * 4;
    int ntot = g_ntiles * 12;

    for (;;) {
        __syncthreads();   // protect smem reuse across tickets
        if (tid == 0) s_tk = atomicAdd(&g_ticket, 1);
        __syncthreads();
        int tk = s_tk;
        if (tk >= ntot) return;

        if (tk < n1) {
            // ================= ffn1 item =================
            int tile = tk >> 2, ntile = tk & 3;
            int e = g_tile_e[tile];
            int tile0 = g_tile_off[tile];
            int cnt = g_cnt[e];
            int nt = min(128, cnt - tile0);
            int base = g_base[e] + tile0;

            if (tid < 128) {
                if (tid < nt) { tok_s[tid] = g_tok[base + tid]; tw_s[tid] = g_tw[base + tid]; }
                else          { tok_s[tid] = g_tok[base];       tw_s[tid] = 0.f; }
            }
            __syncthreads();

            const __half* WqE = g_W1q + ((size_t)e * 512 + (size_t)ntile * 128) * 1024;

            float acc[4][4][4];
#pragma unroll
            for (int a = 0; a < 4; a++)
#pragma unroll
                for (int b = 0; b < 4; b++)
#pragma unroll
                    for (int u = 0; u < 4; u++) acc[a][b][u] = 0.f;

            auto load_chunk = [&](int c, int b) {
                int k0 = c * 64;
                uint32_t bufb = sb + 1024 + b * 32768;
                int c16 = tid & 7, row0 = tid >> 3;
#pragma unroll
                for (int it = 0; it < 4; it++) {
                    int r = row0 + it * 32;
                    uint32_t o = SW128((uint32_t)(r * 128 + c16 * 16));
                    CP16(bufb + o,         g_Xq + (size_t)tok_s[r] * 1024 + k0 + c16 * 8);
                    CP16(bufb + 16384 + o, WqE + (size_t)r * 1024 + k0 + c16 * 8);
                }
            };

            load_chunk(0, 0); CP_COMMIT();
            CP_WAIT0(); __syncthreads();

            for (int c = 0; c < 16; c++) {
                int b = c & 1;
                if (c + 1 < 16) { load_chunk(c + 1, (c + 1) & 1); CP_COMMIT(); }
                uint32_t bufb = sb + 1024 + b * 32768;
#pragma unroll
                for (int kk = 0; kk < 4; kk++) {
                    uint32_t ah[4][4];
#pragma unroll
                    for (int mf = 0; mf < 4; mf++)
                        ldsm4(ldsm_addr(bufb, wm * 64 + mf * 16, kk, lane),
                              ah[mf][0], ah[mf][1], ah[mf][2], ah[mf][3]);
#pragma unroll
                    for (int nf2 = 0; nf2 < 2; nf2++) {
                        uint32_t b0, b1, b2, b3;
                        ldsm4(ldsm_addr(bufb + 16384, wn * 32 + nf2 * 16, kk, lane), b0, b1, b2, b3);
#pragma unroll
                        for (int mf = 0; mf < 4; mf++) {
                            mma16816(acc[mf][nf2 * 2],     ah[mf], b0, b2);
                            mma16816(acc[mf][nf2 * 2 + 1], ah[mf], b1, b3);
                        }
                    }
                }
                if (c + 1 < 16) CP_WAIT0();
                __syncthreads();
            }

            // epilogue: silu * tw -> fp16 H
#pragma unroll
            for (int mf = 0; mf < 4; mf++) {
#pragma unroll
                for (int half = 0; half < 2; half++) {
                    int r = wm * 64 + mf * 16 + (lane >> 2) + half * 8;
                    if (r < nt) {
                        float tw = tw_s[r];
                        int slot = base + r;
#pragma unroll
                        for (int nf = 0; nf < 4; nf++) {
                            int ncol = ntile * 128 + wn * 32 + nf * 8 + (lane & 3) * 2;
                            float v0 = acc[mf][nf][half * 2 + 0];
                            float v1 = acc[mf][nf][half * 2 + 1];
                            v0 = v0 / (1.f + __expf(-v0)) * tw;
                            v1 = v1 / (1.f + __expf(-v1)) * tw;
                            *(uint32_t*)(g_Hq + (size_t)slot * 512 + ncol) =
                                packh2(__float2half_rn(v0), __float2half_rn(v1));
                        }
                    }
                }
            }
            __syncthreads();
            if (tid == 0) { __threadfence(); atomicAdd(&g_ready[tile], 1); }
        } else {
            // ================= ffn2 item =================
            int j = tk - n1;
            int tile = j >> 3, ntile = j & 7;
            int e = g_tile_e[tile];
            int tile0 = g_tile_off[tile];
            int cnt = g_cnt[e];
            int nt = min(128, cnt - tile0);
            int base = g_base[e] + tile0;

            if (tid == 0) {
                while (atomicAdd(&g_ready[tile], 0) < 4) __nanosleep(64);
            }
            __syncthreads();
            __threadfence();

            const __half* WqE = g_W2q + ((size_t)e * 1024 + (size_t)ntile * 128) * 512;

            float acc[4][4][4];
#pragma unroll
            for (int a = 0; a < 4; a++)
#pragma unroll
                for (int b = 0; b < 4; b++)
#pragma unroll
                    for (int u = 0; u < 4; u++) acc[a][b][u] = 0.f;

            auto load_chunk2 = [&](int c, int b) {
                int k0 = c * 64;
                uint32_t bufb = sb + 1024 + b * 32768;
                int c16 = tid & 7, row0 = tid >> 3;
#pragma unroll
                for (int it = 0; it < 4; it++) {
                    int r = row0 + it * 32;
                    int rc = min(r, nt - 1);
                    uint32_t o = SW128((uint32_t)(r * 128 + c16 * 16));
                    CP16(bufb + o,         g_Hq + (size_t)(base + rc) * 512 + k0 + c16 * 8);
                    CP16(bufb + 16384 + o, WqE + (size_t)r * 512 + k0 + c16 * 8);
                }
            };

            load_chunk2(0, 0); CP_COMMIT();
            CP_WAIT0(); __syncthreads();

            for (int c = 0; c < 8; c++) {
                int b = c & 1;
                if (c + 1 < 8) { load_chunk2(c + 1, (c + 1) & 1); CP_COMMIT(); }
                uint32_t bufb = sb + 1024 + b * 32768;
#pragma unroll
                for (int kk = 0; kk < 4; kk++) {
                    uint32_t ah[4][4];
#pragma unroll
                    for (int mf = 0; mf < 4; mf++)
                        ldsm4(ldsm_addr(bufb, wm * 64 + mf * 16, kk, lane),
                              ah[mf][0], ah[mf][1], ah[mf][2], ah[mf][3]);
#pragma unroll
                    for (int nf2 = 0; nf2 < 2; nf2++) {
                        uint32_t b0, b1, b2, b3;
                        ldsm4(ldsm_addr(bufb + 16384, wn * 32 + nf2 * 16, kk, lane), b0, b1, b2, b3);
#pragma unroll
                        for (int mf = 0; mf < 4; mf++) {
                            mma16816(acc[mf][nf2 * 2],     ah[mf], b0, b2);
                            mma16816(acc[mf][nf2 * 2 + 1], ah[mf], b1, b3);
                        }
                    }
                }
                if (c + 1 < 8) CP_WAIT0();
                __syncthreads();
            }

            // epilogue: fp32 partials per slot
#pragma unroll
            for (int mf = 0; mf < 4; mf++) {
#pragma unroll
                for (int half = 0; half < 2; half++) {
                    int r = wm * 64 + mf * 16 + (lane >> 2) + half * 8;
                    if (r < nt) {
                        int slot = base + r;
#pragma unroll
                        for (int nf = 0; nf < 4; nf++) {
                            int ncol = ntile * 128 + wn * 32 + nf * 8 + (lane & 3) * 2;
                            *(float2*)(g_O2 + (size_t)slot * 1024 + ncol) =
                                make_float2(acc[mf][nf][half * 2], acc[mf][nf][half * 2 + 1]);
                        }
                    }
                }
            }
        }
    }
}

// ================= reduce: out[t] = sum_r O2[slot(t,r)] ==========================
__global__ __launch_bounds__(256) void reduce_kernel(float* __restrict__ out) {
    int t = blockIdx.x;
    __shared__ int sl[8];
    if (threadIdx.x < 8) sl[threadIdx.x] = g_slot[t * 8 + threadIdx.x];
    __syncthreads();
    int c = threadIdx.x * 4;
    float4 a = make_float4(0.f, 0.f, 0.f, 0.f);
#pragma unroll
    for (int r = 0; r < 8; r++) {
        float4 v = *(const float4*)(g_O2 + (size_t)sl[r] * 1024 + c);
        a.x += v.x; a.y += v.y; a.z += v.z; a.w += v.w;
    }
    *(float4*)(out + (size_t)t * 1024 + c) = a;
}

// ================= launch ========================================================
extern "C" void kernel_launch(void* const* d_in, const int* in_sizes, int n_in,
                              void* d_out, int out_size) {
    const float* x   = (const float*)d_in[0];
    const float* gw  = (const float*)d_in[1];
    const int*   qw1 = (const int*)d_in[2];
    const int*   qz1 = (const int*)d_in[3];
    const float* sc1 = (const float*)d_in[4];
    const int*   qw2 = (const int*)d_in[5];
    const int*   qz2 = (const int*)d_in[6];
    const float* sc2 = (const float*)d_in[7];
    float* out = (float*)d_out;

    const int DQ_SMEM = 64 * DQ_S * 2;
    cudaFuncSetAttribute(dequant1_t, cudaFuncAttributeMaxDynamicSharedMemorySize, DQ_SMEM);
    cudaFuncSetAttribute(dequant2_t, cudaFuncAttributeMaxDynamicSharedMemorySize, DQ_SMEM);
    cudaFuncSetAttribute(ffn_fused, cudaFuncAttributeMaxDynamicSharedMemorySize, F_SMEM);

    // host-side queries run once (at capture); grid = occupancy * SMs so every
    // persistent CTA is co-resident -> producer/consumer spin cannot deadlock.
    int nsm = 148, occ = 1;
    cudaDeviceGetAttribute(&nsm, cudaDevAttrMultiProcessorCount, 0);
    cudaOccupancyMaxActiveBlocksPerMultiprocessor(&occ, ffn_fused, 256, F_SMEM);
    if (occ < 1) occ = 1;
    int grid = nsm * occ;

    dequant1_t<<<dim3(512, 4), 256, DQ_SMEM>>>(qw1, qz1, sc1);
    dequant2_t<<<dim3(1024, 2), 256, DQ_SMEM>>>(qw2, qz2, sc2);
    router_kernel<<<T_TOK / 4, 256>>>(x, gw);
    scan_kernel<<<1, 1>>>();
    scatter_kernel<<<(T_TOK * TOPK + 255) / 256, 256>>>();
    ffn_fused<<<grid, 256, F_SMEM>>>();
    reduce_kernel<<<T_TOK, 256>>>(out);
}

// round 15
// speedup vs baseline: 1.0690x; 1.0690x over previous
#include <cuda_runtime.h>
#include <cuda_fp16.h>
#include <math.h>
#include <stdint.h>

#define T_TOK 2048
#define HID   1024
#define NEXP  64
#define TOPK  8
#define ISZ   512
#define GRP   128

// ================= helpers ========================================================
__device__ __forceinline__ uint32_t smem_to_u32(const void* p) {
    uint32_t a;
    asm("{ .reg .u64 t; cvta.to.shared.u64 t, %1; cvt.u32.u64 %0, t; }" : "=r"(a) : "l"(p));
    return a;
}
#define SW128(o) ((o) ^ (((o) >> 3) & 0x70))

#define CP16(dst, src) \
    asm volatile("cp.async.cg.shared.global [%0], [%1], 16;" \
                 :: "r"((uint32_t)(dst)), "l"((const void*)(src)) : "memory")
#define CP_COMMIT() asm volatile("cp.async.commit_group;" ::: "memory")
#define CP_WAIT0()  asm volatile("cp.async.wait_group 0;" ::: "memory")
#define CP_WAIT1()  asm volatile("cp.async.wait_group 1;" ::: "memory")

__device__ __forceinline__ void ldsm4(uint32_t addr, uint32_t& r0, uint32_t& r1,
                                      uint32_t& r2, uint32_t& r3) {
    asm volatile("ldmatrix.sync.aligned.m8n8.x4.shared.b16 {%0,%1,%2,%3}, [%4];"
                 : "=r"(r0), "=r"(r1), "=r"(r2), "=r"(r3) : "r"(addr));
}
__device__ __forceinline__ void mma16816(float* c, const uint32_t* a,
                                         uint32_t b0, uint32_t b1) {
    asm volatile("mma.sync.aligned.m16n8k16.row.col.f32.f16.f16.f32 "
                 "{%0,%1,%2,%3}, {%4,%5,%6,%7}, {%8,%9}, {%0,%1,%2,%3};"
                 : "+f"(c[0]), "+f"(c[1]), "+f"(c[2]), "+f"(c[3])
                 : "r"(a[0]), "r"(a[1]), "r"(a[2]), "r"(a[3]), "r"(b0), "r"(b1));
}
// ldsm address: tile rows of 64 fp16 (128 B), SW128-swizzled, base 1024-aligned.
__device__ __forceinline__ uint32_t ldsm_addr(uint32_t tile_base, int R, int kk, int lane) {
    int g = lane >> 3;
    int row = R + ((g & 1) << 3) + (lane & 7);
    uint32_t off = (uint32_t)(row * 128 + kk * 32 + ((g >> 1) << 4));
    return tile_base + SW128(off);
}
__device__ __forceinline__ uint32_t packh2(__half a, __half b) {
    return (uint32_t)__half_as_ushort(a) | ((uint32_t)__half_as_ushort(b) << 16);
}

// ================= device scratch =================================================
__device__ __half g_W1q[33554432];   // [E*I=32768][K=1024] pre-scaled fp16, k-major
__device__ __half g_W2q[33554432];   // [E*H=65536][K=512]
__device__ __half g_Xq[2097152];     // [T=2048][1024]
__device__ __half g_Hq[8388608];     // [16384 slots][512]
__device__ float  g_O2[16777216];    // [16384 slots][1024]
__device__ int   g_topk_idx[T_TOK*TOPK];
__device__ float g_topk_w[T_TOK*TOPK];
__device__ int   g_cnt[NEXP];
__device__ int   g_base[NEXP];
__device__ int   g_pos[NEXP];
__device__ int   g_tok[T_TOK*TOPK];
__device__ float g_tw[T_TOK*TOPK];
__device__ int   g_slot[T_TOK*TOPK];
__device__ int   g_tile_e[256];
__device__ int   g_tile_off[256];
__device__ int   g_ntiles;

// ================= dequant: (q-z)*s -> fp16, transposed k-major ==================
// AWQ nibble j shift = (j>>1)*4 + (j&1)*16; dense column n = c*8+j -> output row n.
#define DQ_S 260
__global__ __launch_bounds__(256) void dequant1_t(
    const int* __restrict__ qw, const int* __restrict__ qz, const float* __restrict__ sc) {
    // folded counter zeroing (runs before router in stream order)
    if (blockIdx.x == 0 && blockIdx.y == 0 && threadIdx.x < NEXP) {
        g_cnt[threadIdx.x] = 0; g_pos[threadIdx.x] = 0;
    }
    int c0 = blockIdx.x * 8;       // word columns (of 4096)
    int k0 = blockIdx.y * 256;     // k tile (of 1024)
    extern __shared__ char smraw[];
    __half* sh = (__half*)smraw;   // [64 n][260 k]
    int tid = threadIdx.x;
    int c = tid & 7, kb = tid >> 3;
#pragma unroll
    for (int r = 0; r < 8; r++) {
        int k = k0 + kb + r * 32;
        unsigned q = (unsigned)qw[(size_t)k * 4096 + c0 + c];
        unsigned z = (unsigned)qz[(size_t)(k >> 7) * 4096 + c0 + c];
        const float* srow = sc + (size_t)(k >> 7) * 32768 + (size_t)(c0 + c) * 8;
#pragma unroll
        for (int j = 0; j < 8; j++) {
            int sh_b = ((j >> 1) << 2) + ((j & 1) << 4);
            float v = (float)((int)((q >> sh_b) & 15u) - (int)((z >> sh_b) & 15u)) * srow[j];
            sh[(c * 8 + j) * DQ_S + (k - k0)] = __float2half_rn(v);
        }
    }
    __syncthreads();
    int n = tid >> 2, qd = tid & 3;
    size_t dst = (size_t)(c0 * 8 + n) * 1024 + k0 + qd * 64;
    const uint2* s2 = (const uint2*)(sh + n * DQ_S + qd * 64);
    uint2* dp = (uint2*)(g_W1q + dst);
#pragma unroll
    for (int u = 0; u < 16; u++) dp[u] = s2[u];
}

__global__ __launch_bounds__(256) void dequant2_t(
    const int* __restrict__ qw, const int* __restrict__ qz, const float* __restrict__ sc) {
    int c0 = blockIdx.x * 8;       // word columns (of 8192)
    int k0 = blockIdx.y * 256;     // k tile (of 512)
    extern __shared__ char smraw[];
    __half* sh = (__half*)smraw;
    int tid = threadIdx.x;
    int c = tid & 7, kb = tid >> 3;
#pragma unroll
    for (int r = 0; r < 8; r++) {
        int k = k0 + kb + r * 32;
        unsigned q = (unsigned)qw[(size_t)k * 8192 + c0 + c];
        unsigned z = (unsigned)qz[(size_t)(k >> 7) * 8192 + c0 + c];
        const float* srow = sc + (size_t)(k >> 7) * 65536 + (size_t)(c0 + c) * 8;
#pragma unroll
        for (int j = 0; j < 8; j++) {
            int sh_b = ((j >> 1) << 2) + ((j & 1) << 4);
            float v = (float)((int)((q >> sh_b) & 15u) - (int)((z >> sh_b) & 15u)) * srow[j];
            sh[(c * 8 + j) * DQ_S + (k - k0)] = __float2half_rn(v);
        }
    }
    __syncthreads();
    int n = tid >> 2, qd = tid & 3;
    size_t dst = (size_t)(c0 * 8 + n) * 512 + k0 + qd * 64;
    const uint2* s2 = (const uint2*)(sh + n * DQ_S + qd * 64);
    uint2* dp = (uint2*)(g_W2q + dst);
#pragma unroll
    for (int u = 0; u < 16; u++) dp[u] = s2[u];
}

// ================= router (fused x -> fp16 conversion) ===========================
__global__ __launch_bounds__(256) void router_kernel(
    const float* __restrict__ x, const float* __restrict__ gw) {
    int tbase = blockIdx.x * 4;
    __shared__ float4 xs4[4][256];
    __shared__ float part[4][64][4];
    __shared__ float logits[4][64];
    int tid = threadIdx.x;
    for (int i = tid; i < 1024; i += 256) {
        int tt = i >> 8, cc = i & 255;
        float4 v = ((const float4*)(x + (size_t)(tbase + tt) * HID))[cc];
        xs4[tt][cc] = v;
        *(uint2*)(g_Xq + (size_t)(tbase + tt) * HID + cc * 4) = make_uint2(
            packh2(__float2half_rn(v.x), __float2half_rn(v.y)),
            packh2(__float2half_rn(v.z), __float2half_rn(v.w)));
    }
    __syncthreads();
    int e = tid >> 2, p = tid & 3;
    const float4* wr = (const float4*)(gw + (size_t)e * HID);
    float s0 = 0, s1 = 0, s2 = 0, s3 = 0;
    for (int k = 0; k < 64; k++) {
        int idx = k * 4 + p;
        float4 w = wr[idx];
        float4 a0 = xs4[0][idx]; s0 += a0.x * w.x + a0.y * w.y + a0.z * w.z + a0.w * w.w;
        float4 a1 = xs4[1][idx]; s1 += a1.x * w.x + a1.y * w.y + a1.z * w.z + a1.w * w.w;
        float4 a2 = xs4[2][idx]; s2 += a2.x * w.x + a2.y * w.y + a2.z * w.z + a2.w * w.w;
        float4 a3 = xs4[3][idx]; s3 += a3.x * w.x + a3.y * w.y + a3.z * w.z + a3.w * w.w;
    }
    part[0][e][p] = s0; part[1][e][p] = s1; part[2][e][p] = s2; part[3][e][p] = s3;
    __syncthreads();
    {
        int tt = tid >> 6, ee = tid & 63;
        logits[tt][ee] = part[tt][ee][0] + part[tt][ee][1] + part[tt][ee][2] + part[tt][ee][3];
    }
    __syncthreads();
    if (tid < 4) {
        int t = tbase + tid;
        unsigned long long used = 0ull;
        int idx[8]; float lv[8];
        for (int r = 0; r < 8; r++) {
            float best = -1e30f; int bi = 0;
            for (int i = 0; i < 64; i++) {
                if (!((used >> i) & 1ull) && logits[tid][i] > best) { best = logits[tid][i]; bi = i; }
            }
            used |= 1ull << bi; idx[r] = bi; lv[r] = best;
        }
        float m = lv[0], sum = 0.f, wk[8];
        for (int r = 0; r < 8; r++) { wk[r] = expf(lv[r] - m); sum += wk[r]; }
        float inv = 1.f / sum;
        for (int r = 0; r < 8; r++) {
            g_topk_idx[t * TOPK + r] = idx[r];
            g_topk_w[t * TOPK + r]   = wk[r] * inv;
            atomicAdd(&g_cnt[idx[r]], 1);
        }
    }
}

// ================= scan (+ tile worklist) + scatter ==============================
__global__ void scan_kernel() {
    int acc = 0;
    for (int i = 0; i < NEXP; i++) { g_base[i] = acc; acc += g_cnt[i]; }
    int tt = 0;
    for (int e = 0; e < NEXP; e++)
        for (int t = 0; t < g_cnt[e]; t += 128) { g_tile_e[tt] = e; g_tile_off[tt] = t; tt++; }
    g_ntiles = tt;
}

__global__ __launch_bounds__(256) void scatter_kernel() {
    int p = blockIdx.x * 256 + threadIdx.x;
    if (p >= T_TOK * TOPK) return;
    int e = g_topk_idx[p];
    int pos = g_base[e] + atomicAdd(&g_pos[e], 1);
    g_tok[pos] = p >> 3;
    g_tw[pos]  = g_topk_w[p];
    g_slot[p]  = pos;
}

// ================= ffn kernels (fp16 HMMA, 3-stage cp.async pipeline) ============
// block tile 128(M) x 128(N), KC=64; 8 warps as 2(M)x4(N) -> warp tile 64x32.
// smem: tok[128]@0, tw[128]@512, 3 buffers @1024: {A 16KB, B 16KB} each.
// 97 KB/CTA x 2 CTAs = 194 KB <= 228 KB/SM -> keeps occupancy 2 with distance-2
// prefetch (~560+ cyc) covering DRAM latency.
#define F_SMEM (1024 + 3 * 32768)

__global__ __launch_bounds__(256, 2) void ffn1_kernel() {
    int tile = blockIdx.x;
    if (tile >= g_ntiles) return;
    int e = g_tile_e[tile];
    int tile0 = g_tile_off[tile];
    int ntile = blockIdx.y;
    int cnt = g_cnt[e];
    int nt = min(128, cnt - tile0);
    int base = g_base[e] + tile0;

    extern __shared__ char smraw[];
    int* tok_s = (int*)smraw;
    float* tw_s = (float*)(smraw + 512);
    uint32_t sb = smem_to_u32(smraw);
    int tid = threadIdx.x, lane = tid & 31, wid = tid >> 5;
    int wm = wid & 1, wn = wid >> 1;

    if (tid < 128) {
        if (tid < nt) { tok_s[tid] = g_tok[base + tid]; tw_s[tid] = g_tw[base + tid]; }
        else          { tok_s[tid] = g_tok[base];       tw_s[tid] = 0.f; }
    }
    __syncthreads();

    const __half* WqE = g_W1q + ((size_t)e * 512 + (size_t)ntile * 128) * 1024;

    float acc[4][4][4];
#pragma unroll
    for (int a = 0; a < 4; a++)
#pragma unroll
        for (int b = 0; b < 4; b++)
#pragma unroll
            for (int u = 0; u < 4; u++) acc[a][b][u] = 0.f;

    auto load_chunk = [&](int c, int b) {
        int k0 = c * 64;
        uint32_t bufb = sb + 1024 + b * 32768;
        int c16 = tid & 7, row0 = tid >> 3;
#pragma unroll
        for (int it = 0; it < 4; it++) {
            int r = row0 + it * 32;
            uint32_t o = SW128((uint32_t)(r * 128 + c16 * 16));
            CP16(bufb + o,         g_Xq + (size_t)tok_s[r] * 1024 + k0 + c16 * 8);
            CP16(bufb + 16384 + o, WqE + (size_t)r * 1024 + k0 + c16 * 8);
        }
    };

    load_chunk(0, 0); CP_COMMIT();
    load_chunk(1, 1); CP_COMMIT();

    const int NC = 16;
    for (int c = 0; c < NC; c++) {
        if (c < NC - 1) CP_WAIT1(); else CP_WAIT0();
        __syncthreads();
        uint32_t bufb = sb + 1024 + (c % 3) * 32768;
#pragma unroll
        for (int kk = 0; kk < 4; kk++) {
            uint32_t ah[4][4];
#pragma unroll
            for (int mf = 0; mf < 4; mf++)
                ldsm4(ldsm_addr(bufb, wm * 64 + mf * 16, kk, lane),
                      ah[mf][0], ah[mf][1], ah[mf][2], ah[mf][3]);
#pragma unroll
            for (int nf2 = 0; nf2 < 2; nf2++) {
                uint32_t b0, b1, b2, b3;
                ldsm4(ldsm_addr(bufb + 16384, wn * 32 + nf2 * 16, kk, lane), b0, b1, b2, b3);
#pragma unroll
                for (int mf = 0; mf < 4; mf++) {
                    mma16816(acc[mf][nf2 * 2],     ah[mf], b0, b2);
                    mma16816(acc[mf][nf2 * 2 + 1], ah[mf], b1, b3);
                }
            }
        }
        if (c + 2 < NC) { load_chunk(c + 2, (c + 2) % 3); CP_COMMIT(); }
    }

    // epilogue: silu * tw -> fp16 H
#pragma unroll
    for (int mf = 0; mf < 4; mf++) {
#pragma unroll
        for (int half = 0; half < 2; half++) {
            int r = wm * 64 + mf * 16 + (lane >> 2) + half * 8;
            if (r < nt) {
                float tw = tw_s[r];
                int slot = base + r;
#pragma unroll
                for (int nf = 0; nf < 4; nf++) {
                    int ncol = ntile * 128 + wn * 32 + nf * 8 + (lane & 3) * 2;
                    float v0 = acc[mf][nf][half * 2 + 0];
                    float v1 = acc[mf][nf][half * 2 + 1];
                    v0 = v0 / (1.f + __expf(-v0)) * tw;
                    v1 = v1 / (1.f + __expf(-v1)) * tw;
                    *(uint32_t*)(g_Hq + (size_t)slot * 512 + ncol) =
                        packh2(__float2half_rn(v0), __float2half_rn(v1));
                }
            }
        }
    }
}

__global__ __launch_bounds__(256, 2) void ffn2_kernel() {
    int tile = blockIdx.x;
    if (tile >= g_ntiles) return;
    int e = g_tile_e[tile];
    int tile0 = g_tile_off[tile];
    int ntile = blockIdx.y;
    int cnt = g_cnt[e];
    int nt = min(128, cnt - tile0);
    int base = g_base[e] + tile0;

    extern __shared__ char smraw[];
    uint32_t sb = smem_to_u32(smraw);
    int tid = threadIdx.x, lane = tid & 31, wid = tid >> 5;
    int wm = wid & 1, wn = wid >> 1;

    const __half* WqE = g_W2q + ((size_t)e * 1024 + (size_t)ntile * 128) * 512;

    float acc[4][4][4];
#pragma unroll
    for (int a = 0; a < 4; a++)
#pragma unroll
        for (int b = 0; b < 4; b++)
#pragma unroll
            for (int u = 0; u < 4; u++) acc[a][b][u] = 0.f;

    auto load_chunk = [&](int c, int b) {
        int k0 = c * 64;
        uint32_t bufb = sb + 1024 + b * 32768;
        int c16 = tid & 7, row0 = tid >> 3;
#pragma unroll
        for (int it = 0; it < 4; it++) {
            int r = row0 + it * 32;
            int rc = min(r, nt - 1);
            uint32_t o = SW128((uint32_t)(r * 128 + c16 * 16));
            CP16(bufb + o,         g_Hq + (size_t)(base + rc) * 512 + k0 + c16 * 8);
            CP16(bufb + 16384 + o, WqE + (size_t)r * 512 + k0 + c16 * 8);
        }
    };

    load_chunk(0, 0); CP_COMMIT();
    load_chunk(1, 1); CP_COMMIT();

    const int NC = 8;
    for (int c = 0; c < NC; c++) {
        if (c < NC - 1) CP_WAIT1(); else CP_WAIT0();
        __syncthreads();
        uint32_t bufb = sb + 1024 + (c % 3) * 32768;
#pragma unroll
        for (int kk = 0; kk < 4; kk++) {
            uint32_t ah[4][4];
#pragma unroll
            for (int mf = 0; mf < 4; mf++)
                ldsm4(ldsm_addr(bufb, wm * 64 + mf * 16, kk, lane),
                      ah[mf][0], ah[mf][1], ah[mf][2], ah[mf][3]);
#pragma unroll
            for (int nf2 = 0; nf2 < 2; nf2++) {
                uint32_t b0, b1, b2, b3;
                ldsm4(ldsm_addr(bufb + 16384, wn * 32 + nf2 * 16, kk, lane), b0, b1, b2, b3);
#pragma unroll
                for (int mf = 0; mf < 4; mf++) {
                    mma16816(acc[mf][nf2 * 2],     ah[mf], b0, b2);
                    mma16816(acc[mf][nf2 * 2 + 1], ah[mf], b1, b3);
                }
            }
        }
        if (c + 2 < NC) { load_chunk(c + 2, (c + 2) % 3); CP_COMMIT(); }
    }

    // epilogue: fp32 partials per slot
#pragma unroll
    for (int mf = 0; mf < 4; mf++) {
#pragma unroll
        for (int half = 0; half < 2; half++) {
            int r = wm * 64 + mf * 16 + (lane >> 2) + half * 8;
            if (r < nt) {
                int slot = base + r;
#pragma unroll
                for (int nf = 0; nf < 4; nf++) {
                    int ncol = ntile * 128 + wn * 32 + nf * 8 + (lane & 3) * 2;
                    *(float2*)(g_O2 + (size_t)slot * 1024 + ncol) =
                        make_float2(acc[mf][nf][half * 2], acc[mf][nf][half * 2 + 1]);
                }
            }
        }
    }
}

// ================= reduce: out[t] = sum_r O2[slot(t,r)] ==========================
__global__ __launch_bounds__(256) void reduce_kernel(float* __restrict__ out) {
    int t = blockIdx.x;
    __shared__ int sl[8];
    if (threadIdx.x < 8) sl[threadIdx.x] = g_slot[t * 8 + threadIdx.x];
    __syncthreads();
    int c = threadIdx.x * 4;
    float4 a = make_float4(0.f, 0.f, 0.f, 0.f);
#pragma unroll
    for (int r = 0; r < 8; r++) {
        float4 v = *(const float4*)(g_O2 + (size_t)sl[r] * 1024 + c);
        a.x += v.x; a.y += v.y; a.z += v.z; a.w += v.w;
    }
    *(float4*)(out + (size_t)t * 1024 + c) = a;
}

// ================= launch ========================================================
extern "C" void kernel_launch(void* const* d_in, const int* in_sizes, int n_in,
                              void* d_out, int out_size) {
    const float* x   = (const float*)d_in[0];
    const float* gw  = (const float*)d_in[1];
    const int*   qw1 = (const int*)d_in[2];
    const int*   qz1 = (const int*)d_in[3];
    const float* sc1 = (const float*)d_in[4];
    const int*   qw2 = (const int*)d_in[5];
    const int*   qz2 = (const int*)d_in[6];
    const float* sc2 = (const float*)d_in[7];
    float* out = (float*)d_out;

    const int DQ_SMEM = 64 * DQ_S * 2;
    cudaFuncSetAttribute(dequant1_t, cudaFuncAttributeMaxDynamicSharedMemorySize, DQ_SMEM);
    cudaFuncSetAttribute(dequant2_t, cudaFuncAttributeMaxDynamicSharedMemorySize, DQ_SMEM);
    cudaFuncSetAttribute(ffn1_kernel, cudaFuncAttributeMaxDynamicSharedMemorySize, F_SMEM);
    cudaFuncSetAttribute(ffn2_kernel, cudaFuncAttributeMaxDynamicSharedMemorySize, F_SMEM);

    dequant1_t<<<dim3(512, 4), 256, DQ_SMEM>>>(qw1, qz1, sc1);
    dequant2_t<<<dim3(1024, 2), 256, DQ_SMEM>>>(qw2, qz2, sc2);
    router_kernel<<<T_TOK / 4, 256>>>(x, gw);
    scan_kernel<<<1, 1>>>();
    scatter_kernel<<<(T_TOK * TOPK + 255) / 256, 256>>>();
    ffn1_kernel<<<dim3(192, 4), 256, F_SMEM>>>();
    ffn2_kernel<<<dim3(192, 8), 256, F_SMEM>>>();
    reduce_kernel<<<T_TOK, 256>>>(out);
}

// round 16
// speedup vs baseline: 1.2040x; 1.1263x over previous
#include <cuda_runtime.h>
#include <cuda_fp16.h>
#include <math.h>
#include <stdint.h>

#define T_TOK 2048
#define HID   1024
#define NEXP  64
#define TOPK  8
#define ISZ   512
#define GRP   128

// ================= helpers ========================================================
__device__ __forceinline__ uint32_t smem_to_u32(const void* p) {
    uint32_t a;
    asm("{ .reg .u64 t; cvta.to.shared.u64 t, %1; cvt.u32.u64 %0, t; }" : "=r"(a) : "l"(p));
    return a;
}
#define SW128(o) ((o) ^ (((o) >> 3) & 0x70))

#define CP16(dst, src) \
    asm volatile("cp.async.cg.shared.global [%0], [%1], 16;" \
                 :: "r"((uint32_t)(dst)), "l"((const void*)(src)) : "memory")
#define CP_COMMIT() asm volatile("cp.async.commit_group;" ::: "memory")
#define CP_WAIT0()  asm volatile("cp.async.wait_group 0;" ::: "memory")
#define CP_WAIT1()  asm volatile("cp.async.wait_group 1;" ::: "memory")

__device__ __forceinline__ void ldsm4(uint32_t addr, uint32_t& r0, uint32_t& r1,
                                      uint32_t& r2, uint32_t& r3) {
    asm volatile("ldmatrix.sync.aligned.m8n8.x4.shared.b16 {%0,%1,%2,%3}, [%4];"
                 : "=r"(r0), "=r"(r1), "=r"(r2), "=r"(r3) : "r"(addr));
}
__device__ __forceinline__ void mma16816(float* c, const uint32_t* a,
                                         uint32_t b0, uint32_t b1) {
    asm volatile("mma.sync.aligned.m16n8k16.row.col.f32.f16.f16.f32 "
                 "{%0,%1,%2,%3}, {%4,%5,%6,%7}, {%8,%9}, {%0,%1,%2,%3};"
                 : "+f"(c[0]), "+f"(c[1]), "+f"(c[2]), "+f"(c[3])
                 : "r"(a[0]), "r"(a[1]), "r"(a[2]), "r"(a[3]), "r"(b0), "r"(b1));
}
// ldsm address: tile rows of 64 fp16 (128 B), SW128-swizzled, base 1024-aligned.
__device__ __forceinline__ uint32_t ldsm_addr(uint32_t tile_base, int R, int kk, int lane) {
    int g = lane >> 3;
    int row = R + ((g & 1) << 3) + (lane & 7);
    uint32_t off = (uint32_t)(row * 128 + kk * 32 + ((g >> 1) << 4));
    return tile_base + SW128(off);
}
__device__ __forceinline__ uint32_t packh2(__half a, __half b) {
    return (uint32_t)__half_as_ushort(a) | ((uint32_t)__half_as_ushort(b) << 16);
}

// ================= device scratch =================================================
__device__ __half g_W1q[33554432];   // [E*I=32768][K=1024] pre-scaled fp16, k-major
__device__ __half g_W2q[33554432];   // [E*H=65536][K=512]
__device__ __half g_Xq[2097152];     // [T=2048][1024]
__device__ __half g_Hq[8388608];     // [16384 slots][512]
__device__ float  g_O2[16777216];    // [16384 slots][1024]
__device__ int   g_topk_idx[T_TOK*TOPK];
__device__ float g_topk_w[T_TOK*TOPK];
__device__ int   g_cnt[NEXP];
__device__ int   g_base[NEXP];
__device__ int   g_pos[NEXP];
__device__ int   g_tok[T_TOK*TOPK];
__device__ float g_tw[T_TOK*TOPK];
__device__ int   g_slot[T_TOK*TOPK];
__device__ int   g_tile_e[256];
__device__ int   g_tile_off[256];
__device__ int   g_ntiles;

// ================= dequant: (q-z)*s -> fp16, transposed k-major ==================
// AWQ nibble j shift = (j>>1)*4 + (j&1)*16; dense column n = c*8+j -> output row n.
#define DQ_S 260
__global__ __launch_bounds__(256) void dequant1_t(
    const int* __restrict__ qw, const int* __restrict__ qz, const float* __restrict__ sc) {
    int c0 = blockIdx.x * 8;       // word columns (of 4096)
    int k0 = blockIdx.y * 256;     // k tile (of 1024)
    extern __shared__ char smraw[];
    __half* sh = (__half*)smraw;   // [64 n][260 k]
    int tid = threadIdx.x;
    int c = tid & 7, kb = tid >> 3;
#pragma unroll
    for (int r = 0; r < 8; r++) {
        int k = k0 + kb + r * 32;
        unsigned q = (unsigned)qw[(size_t)k * 4096 + c0 + c];
        unsigned z = (unsigned)qz[(size_t)(k >> 7) * 4096 + c0 + c];
        const float* srow = sc + (size_t)(k >> 7) * 32768 + (size_t)(c0 + c) * 8;
#pragma unroll
        for (int j = 0; j < 8; j++) {
            int sh_b = ((j >> 1) << 2) + ((j & 1) << 4);
            float v = (float)((int)((q >> sh_b) & 15u) - (int)((z >> sh_b) & 15u)) * srow[j];
            sh[(c * 8 + j) * DQ_S + (k - k0)] = __float2half_rn(v);
        }
    }
    __syncthreads();
    int n = tid >> 2, qd = tid & 3;
    size_t dst = (size_t)(c0 * 8 + n) * 1024 + k0 + qd * 64;
    const uint2* s2 = (const uint2*)(sh + n * DQ_S + qd * 64);
    uint2* dp = (uint2*)(g_W1q + dst);
#pragma unroll
    for (int u = 0; u < 16; u++) dp[u] = s2[u];
}

__global__ __launch_bounds__(256) void dequant2_t(
    const int* __restrict__ qw, const int* __restrict__ qz, const float* __restrict__ sc) {
    int c0 = blockIdx.x * 8;       // word columns (of 8192)
    int k0 = blockIdx.y * 256;     // k tile (of 512)
    extern __shared__ char smraw[];
    __half* sh = (__half*)smraw;
    int tid = threadIdx.x;
    int c = tid & 7, kb = tid >> 3;
#pragma unroll
    for (int r = 0; r < 8; r++) {
        int k = k0 + kb + r * 32;
        unsigned q = (unsigned)qw[(size_t)k * 8192 + c0 + c];
        unsigned z = (unsigned)qz[(size_t)(k >> 7) * 8192 + c0 + c];
        const float* srow = sc + (size_t)(k >> 7) * 65536 + (size_t)(c0 + c) * 8;
#pragma unroll
        for (int j = 0; j < 8; j++) {
            int sh_b = ((j >> 1) << 2) + ((j & 1) << 4);
            float v = (float)((int)((q >> sh_b) & 15u) - (int)((z >> sh_b) & 15u)) * srow[j];
            sh[(c * 8 + j) * DQ_S + (k - k0)] = __float2half_rn(v);
        }
    }
    __syncthreads();
    int n = tid >> 2, qd = tid & 3;
    size_t dst = (size_t)(c0 * 8 + n) * 512 + k0 + qd * 64;
    const uint2* s2 = (const uint2*)(sh + n * DQ_S + qd * 64);
    uint2* dp = (uint2*)(g_W2q + dst);
#pragma unroll
    for (int u = 0; u < 16; u++) dp[u] = s2[u];
}

// ================= router (fused x -> fp16 conversion) ===========================
__global__ __launch_bounds__(256) void router_kernel(
    const float* __restrict__ x, const float* __restrict__ gw) {
    int tbase = blockIdx.x * 4;
    __shared__ float4 xs4[4][256];
    __shared__ float part[4][64][4];
    __shared__ float logits[4][64];
    int tid = threadIdx.x;
    for (int i = tid; i < 1024; i += 256) {
        int tt = i >> 8, cc = i & 255;
        float4 v = ((const float4*)(x + (size_t)(tbase + tt) * HID))[cc];
        xs4[tt][cc] = v;
        *(uint2*)(g_Xq + (size_t)(tbase + tt) * HID + cc * 4) = make_uint2(
            packh2(__float2half_rn(v.x), __float2half_rn(v.y)),
            packh2(__float2half_rn(v.z), __float2half_rn(v.w)));
    }
    __syncthreads();
    int e = tid >> 2, p = tid & 3;
    const float4* wr = (const float4*)(gw + (size_t)e * HID);
    float s0 = 0, s1 = 0, s2 = 0, s3 = 0;
    for (int k = 0; k < 64; k++) {
        int idx = k * 4 + p;
        float4 w = wr[idx];
        float4 a0 = xs4[0][idx]; s0 += a0.x * w.x + a0.y * w.y + a0.z * w.z + a0.w * w.w;
        float4 a1 = xs4[1][idx]; s1 += a1.x * w.x + a1.y * w.y + a1.z * w.z + a1.w * w.w;
        float4 a2 = xs4[2][idx]; s2 += a2.x * w.x + a2.y * w.y + a2.z * w.z + a2.w * w.w;
        float4 a3 = xs4[3][idx]; s3 += a3.x * w.x + a3.y * w.y + a3.z * w.z + a3.w * w.w;
    }
    part[0][e][p] = s0; part[1][e][p] = s1; part[2][e][p] = s2; part[3][e][p] = s3;
    __syncthreads();
    {
        int tt = tid >> 6, ee = tid & 63;
        logits[tt][ee] = part[tt][ee][0] + part[tt][ee][1] + part[tt][ee][2] + part[tt][ee][3];
    }
    __syncthreads();
    if (tid < 4) {
        int t = tbase + tid;
        unsigned long long used = 0ull;
        int idx[8]; float lv[8];
        for (int r = 0; r < 8; r++) {
            float best = -1e30f; int bi = 0;
            for (int i = 0; i < 64; i++) {
                if (!((used >> i) & 1ull) && logits[tid][i] > best) { best = logits[tid][i]; bi = i; }
            }
            used |= 1ull << bi; idx[r] = bi; lv[r] = best;
        }
        float m = lv[0], sum = 0.f, wk[8];
        for (int r = 0; r < 8; r++) { wk[r] = expf(lv[r] - m); sum += wk[r]; }
        float inv = 1.f / sum;
        for (int r = 0; r < 8; r++) {
            g_topk_idx[t * TOPK + r] = idx[r];
            g_topk_w[t * TOPK + r]   = wk[r] * inv;
            atomicAdd(&g_cnt[idx[r]], 1);
        }
    }
}

// ================= parallel scan (+ tile worklist) + scatter =====================
__global__ __launch_bounds__(64) void scan_kernel() {
    __shared__ int a[64], b[64];
    int e = threadIdx.x;
    int c = g_cnt[e];
    int tc = (c + 127) >> 7;
    a[e] = c; b[e] = tc;
    __syncthreads();
#pragma unroll
    for (int d = 1; d < 64; d <<= 1) {
        int va = (e >= d) ? a[e - d] : 0;
        int vb = (e >= d) ? b[e - d] : 0;
        __syncthreads();
        a[e] += va; b[e] += vb;
        __syncthreads();
    }
    g_base[e] = a[e] - c;
    int tb = b[e] - tc;
    for (int i = 0; i < tc; i++) { g_tile_e[tb + i] = e; g_tile_off[tb + i] = i * 128; }
    if (e == 63) g_ntiles = b[63];
}

__global__ __launch_bounds__(256) void scatter_kernel() {
    int p = blockIdx.x * 256 + threadIdx.x;
    if (p >= T_TOK * TOPK) return;
    int e = g_topk_idx[p];
    int pos = g_base[e] + atomicAdd(&g_pos[e], 1);
    g_tok[pos] = p >> 3;
    g_tw[pos]  = g_topk_w[p];
    g_slot[p]  = pos;
}

// ================= ffn kernels (fp16 HMMA, 3-stage cp.async pipeline) ============
// block tile 128(M) x 128(N), KC=64; 8 warps as 2(M)x4(N) -> warp tile 64x32.
// smem: tok[128]@0, tw[128]@512, 3 buffers @1024: {A 16KB, B 16KB} each.
#define F_SMEM (1024 + 3 * 32768)

__global__ __launch_bounds__(256, 2) void ffn1_kernel() {
    int tile = blockIdx.x;
    if (tile >= g_ntiles) return;
    int e = g_tile_e[tile];
    int tile0 = g_tile_off[tile];
    int ntile = blockIdx.y;
    int cnt = g_cnt[e];
    int nt = min(128, cnt - tile0);
    int base = g_base[e] + tile0;

    extern __shared__ char smraw[];
    int* tok_s = (int*)smraw;
    float* tw_s = (float*)(smraw + 512);
    uint32_t sb = smem_to_u32(smraw);
    int tid = threadIdx.x, lane = tid & 31, wid = tid >> 5;
    int wm = wid & 1, wn = wid >> 1;

    if (tid < 128) {
        if (tid < nt) { tok_s[tid] = g_tok[base + tid]; tw_s[tid] = g_tw[base + tid]; }
        else          { tok_s[tid] = g_tok[base];       tw_s[tid] = 0.f; }
    }
    __syncthreads();

    const __half* WqE = g_W1q + ((size_t)e * 512 + (size_t)ntile * 128) * 1024;

    float acc[4][4][4];
#pragma unroll
    for (int a = 0; a < 4; a++)
#pragma unroll
        for (int b = 0; b < 4; b++)
#pragma unroll
            for (int u = 0; u < 4; u++) acc[a][b][u] = 0.f;

    auto load_chunk = [&](int c, int b) {
        int k0 = c * 64;
        uint32_t bufb = sb + 1024 + b * 32768;
        int c16 = tid & 7, row0 = tid >> 3;
#pragma unroll
        for (int it = 0; it < 4; it++) {
            int r = row0 + it * 32;
            uint32_t o = SW128((uint32_t)(r * 128 + c16 * 16));
            CP16(bufb + o,         g_Xq + (size_t)tok_s[r] * 1024 + k0 + c16 * 8);
            CP16(bufb + 16384 + o, WqE + (size_t)r * 1024 + k0 + c16 * 8);
        }
    };

    load_chunk(0, 0); CP_COMMIT();
    load_chunk(1, 1); CP_COMMIT();

    const int NC = 16;
    for (int c = 0; c < NC; c++) {
        if (c < NC - 1) CP_WAIT1(); else CP_WAIT0();
        __syncthreads();
        uint32_t bufb = sb + 1024 + (c % 3) * 32768;
#pragma unroll
        for (int kk = 0; kk < 4; kk++) {
            uint32_t ah[4][4];
#pragma unroll
            for (int mf = 0; mf < 4; mf++)
                ldsm4(ldsm_addr(bufb, wm * 64 + mf * 16, kk, lane),
                      ah[mf][0], ah[mf][1], ah[mf][2], ah[mf][3]);
#pragma unroll
            for (int nf2 = 0; nf2 < 2; nf2++) {
                uint32_t b0, b1, b2, b3;
                ldsm4(ldsm_addr(bufb + 16384, wn * 32 + nf2 * 16, kk, lane), b0, b1, b2, b3);
#pragma unroll
                for (int mf = 0; mf < 4; mf++) {
                    mma16816(acc[mf][nf2 * 2],     ah[mf], b0, b2);
                    mma16816(acc[mf][nf2 * 2 + 1], ah[mf], b1, b3);
                }
            }
        }
        if (c + 2 < NC) { load_chunk(c + 2, (c + 2) % 3); CP_COMMIT(); }
    }

    // epilogue: silu * tw -> fp16 H
#pragma unroll
    for (int mf = 0; mf < 4; mf++) {
#pragma unroll
        for (int half = 0; half < 2; half++) {
            int r = wm * 64 + mf * 16 + (lane >> 2) + half * 8;
            if (r < nt) {
                float tw = tw_s[r];
                int slot = base + r;
#pragma unroll
                for (int nf = 0; nf < 4; nf++) {
                    int ncol = ntile * 128 + wn * 32 + nf * 8 + (lane & 3) * 2;
                    float v0 = acc[mf][nf][half * 2 + 0];
                    float v1 = acc[mf][nf][half * 2 + 1];
                    v0 = v0 / (1.f + __expf(-v0)) * tw;
                    v1 = v1 / (1.f + __expf(-v1)) * tw;
                    *(uint32_t*)(g_Hq + (size_t)slot * 512 + ncol) =
                        packh2(__float2half_rn(v0), __float2half_rn(v1));
                }
            }
        }
    }
}

__global__ __launch_bounds__(256, 2) void ffn2_kernel() {
    int tile = blockIdx.x;
    if (tile >= g_ntiles) return;
    int e = g_tile_e[tile];
    int tile0 = g_tile_off[tile];
    int ntile = blockIdx.y;
    int cnt = g_cnt[e];
    int nt = min(128, cnt - tile0);
    int base = g_base[e] + tile0;

    extern __shared__ char smraw[];
    uint32_t sb = smem_to_u32(smraw);
    int tid = threadIdx.x, lane = tid & 31, wid = tid >> 5;
    int wm = wid & 1, wn = wid >> 1;

    const __half* WqE = g_W2q + ((size_t)e * 1024 + (size_t)ntile * 128) * 512;

    float acc[4][4][4];
#pragma unroll
    for (int a = 0; a < 4; a++)
#pragma unroll
        for (int b = 0; b < 4; b++)
#pragma unroll
            for (int u = 0; u < 4; u++) acc[a][b][u] = 0.f;

    auto load_chunk = [&](int c, int b) {
        int k0 = c * 64;
        uint32_t bufb = sb + 1024 + b * 32768;
        int c16 = tid & 7, row0 = tid >> 3;
#pragma unroll
        for (int it = 0; it < 4; it++) {
            int r = row0 + it * 32;
            int rc = min(r, nt - 1);
            uint32_t o = SW128((uint32_t)(r * 128 + c16 * 16));
            CP16(bufb + o,         g_Hq + (size_t)(base + rc) * 512 + k0 + c16 * 8);
            CP16(bufb + 16384 + o, WqE + (size_t)r * 512 + k0 + c16 * 8);
        }
    };

    load_chunk(0, 0); CP_COMMIT();
    load_chunk(1, 1); CP_COMMIT();

    const int NC = 8;
    for (int c = 0; c < NC; c++) {
        if (c < NC - 1) CP_WAIT1(); else CP_WAIT0();
        __syncthreads();
        uint32_t bufb = sb + 1024 + (c % 3) * 32768;
#pragma unroll
        for (int kk = 0; kk < 4; kk++) {
            uint32_t ah[4][4];
#pragma unroll
            for (int mf = 0; mf < 4; mf++)
                ldsm4(ldsm_addr(bufb, wm * 64 + mf * 16, kk, lane),
                      ah[mf][0], ah[mf][1], ah[mf][2], ah[mf][3]);
#pragma unroll
            for (int nf2 = 0; nf2 < 2; nf2++) {
                uint32_t b0, b1, b2, b3;
                ldsm4(ldsm_addr(bufb + 16384, wn * 32 + nf2 * 16, kk, lane), b0, b1, b2, b3);
#pragma unroll
                for (int mf = 0; mf < 4; mf++) {
                    mma16816(acc[mf][nf2 * 2],     ah[mf], b0, b2);
                    mma16816(acc[mf][nf2 * 2 + 1], ah[mf], b1, b3);
                }
            }
        }
        if (c + 2 < NC) { load_chunk(c + 2, (c + 2) % 3); CP_COMMIT(); }
    }

    // epilogue: fp32 partials per slot
#pragma unroll
    for (int mf = 0; mf < 4; mf++) {
#pragma unroll
        for (int half = 0; half < 2; half++) {
            int r = wm * 64 + mf * 16 + (lane >> 2) + half * 8;
            if (r < nt) {
                int slot = base + r;
#pragma unroll
                for (int nf = 0; nf < 4; nf++) {
                    int ncol = ntile * 128 + wn * 32 + nf * 8 + (lane & 3) * 2;
                    *(float2*)(g_O2 + (size_t)slot * 1024 + ncol) =
                        make_float2(acc[mf][nf][half * 2], acc[mf][nf][half * 2 + 1]);
                }
            }
        }
    }
}

// ================= reduce: out[t] = sum_r O2[slot(t,r)] ==========================
__global__ __launch_bounds__(256) void reduce_kernel(float* __restrict__ out) {
    int t = blockIdx.x;
    __shared__ int sl[8];
    if (threadIdx.x < 8) sl[threadIdx.x] = g_slot[t * 8 + threadIdx.x];
    __syncthreads();
    int c = threadIdx.x * 4;
    float4 a = make_float4(0.f, 0.f, 0.f, 0.f);
#pragma unroll
    for (int r = 0; r < 8; r++) {
        float4 v = *(const float4*)(g_O2 + (size_t)sl[r] * 1024 + c);
        a.x += v.x; a.y += v.y; a.z += v.z; a.w += v.w;
    }
    *(float4*)(out + (size_t)t * 1024 + c) = a;
}

// ================= launch ========================================================
extern "C" void kernel_launch(void* const* d_in, const int* in_sizes, int n_in,
                              void* d_out, int out_size) {
    const float* x   = (const float*)d_in[0];
    const float* gw  = (const float*)d_in[1];
    const int*   qw1 = (const int*)d_in[2];
    const int*   qz1 = (const int*)d_in[3];
    const float* sc1 = (const float*)d_in[4];
    const int*   qw2 = (const int*)d_in[5];
    const int*   qz2 = (const int*)d_in[6];
    const float* sc2 = (const float*)d_in[7];
    float* out = (float*)d_out;

    // one-time host-object setup (streams/events are host state, not device mem)
    static cudaStream_t s2 = nullptr;
    static cudaEvent_t evFork = nullptr, evDeq = nullptr;
    if (!s2) {
        cudaStreamCreateWithFlags(&s2, cudaStreamNonBlocking);
        cudaEventCreateWithFlags(&evFork, cudaEventDisableTiming);
        cudaEventCreateWithFlags(&evDeq, cudaEventDisableTiming);
    }

    const int DQ_SMEM = 64 * DQ_S * 2;
    cudaFuncSetAttribute(dequant1_t, cudaFuncAttributeMaxDynamicSharedMemorySize, DQ_SMEM);
    cudaFuncSetAttribute(dequant2_t, cudaFuncAttributeMaxDynamicSharedMemorySize, DQ_SMEM);
    cudaFuncSetAttribute(ffn1_kernel, cudaFuncAttributeMaxDynamicSharedMemorySize, F_SMEM);
    cudaFuncSetAttribute(ffn2_kernel, cudaFuncAttributeMaxDynamicSharedMemorySize, F_SMEM);

    // zero routing counters on the capture stream (before router)
    void* cnt_addr = nullptr; void* pos_addr = nullptr;
    cudaGetSymbolAddress(&cnt_addr, g_cnt);
    cudaGetSymbolAddress(&pos_addr, g_pos);
    cudaMemsetAsync(cnt_addr, 0, NEXP * sizeof(int), 0);
    cudaMemsetAsync(pos_addr, 0, NEXP * sizeof(int), 0);

    // fork: dequant chain on s2, routing chain on capture stream
    cudaEventRecord(evFork, 0);
    cudaStreamWaitEvent(s2, evFork, 0);
    dequant1_t<<<dim3(512, 4), 256, DQ_SMEM, s2>>>(qw1, qz1, sc1);
    dequant2_t<<<dim3(1024, 2), 256, DQ_SMEM, s2>>>(qw2, qz2, sc2);
    cudaEventRecord(evDeq, s2);

    router_kernel<<<T_TOK / 4, 256>>>(x, gw);
    scan_kernel<<<1, 64>>>();
    scatter_kernel<<<(T_TOK * TOPK + 255) / 256, 256>>>();

    // join: ffn needs dequantized weights + routing
    cudaStreamWaitEvent(0, evDeq, 0);
    ffn1_kernel<<<dim3(192, 4), 256, F_SMEM>>>();
    ffn2_kernel<<<dim3(192, 8), 256, F_SMEM>>>();
    reduce_kernel<<<T_TOK, 256>>>(out);
}